// round 7
// baseline (speedup 1.0000x reference)
#include <cuda_runtime.h>
#include <cuda_fp16.h>
#include <cstdint>

#define NB 2
#define NS 256
#define NE 512
#define NH 8
#define NDH 64
#define NTC 768
#define NL 8192
#define NOLD 6144
#define FSPLIT 4
#define FKT 128
#define NCH2 (NL/FKT/FSPLIT)   // 16 chunks per flash block

// Scratch (device globals)
__device__ __half g_x[NB*NS*NE];        // x in fp16
__device__ __half g_q[NB*NS*NE];        // Q proj (scaled by 0.125*log2e)
__device__ __half g_k[NB*NL*NDH];       // concat K        [b][l][d]
__device__ __half g_v[NB*NDH*NL];       // concat V TRANSPOSED [b][d][l]
__device__ __half g_attn_h[NB*NS*NE];   // merged attention (fp16)
__device__ float  g_po[FSPLIT*NB*NS*NE];
__device__ float  g_pl[FSPLIT*NB*NH*NS];

// ---------------------------------------------------------------------------
__device__ __forceinline__ void mma_f16(float c[4], const uint32_t a[4],
                                        const uint32_t b[2]) {
    asm volatile(
        "mma.sync.aligned.m16n8k16.row.col.f32.f16.f16.f32 "
        "{%0,%1,%2,%3}, {%4,%5,%6,%7}, {%8,%9}, {%0,%1,%2,%3};"
        : "+f"(c[0]), "+f"(c[1]), "+f"(c[2]), "+f"(c[3])
        : "r"(a[0]), "r"(a[1]), "r"(a[2]), "r"(a[3]), "r"(b[0]), "r"(b[1]));
}
__device__ __forceinline__ uint32_t packh2(float x, float y) {
    __half2 h = __floats2half2_rn(x, y);
    return *(uint32_t*)&h;
}
__device__ __forceinline__ uint32_t ex2h2(uint32_t s) {
    uint32_t r;
    asm("ex2.approx.f16x2 %0, %1;" : "=r"(r) : "r"(s));
    return r;
}
#define CP16(d, s) asm volatile("cp.async.cg.shared.global [%0], [%1], 16;" \
                                :: "r"(d), "l"(s))
#define CP_COMMIT() asm volatile("cp.async.commit_group;")
#define CP_WAIT0()  asm volatile("cp.async.wait_group 0;")

// ---------------------------------------------------------------------------
// x -> fp16
__global__ __launch_bounds__(256) void convert_x_kernel(const float4* __restrict__ x)
{
    int i = blockIdx.x*256 + threadIdx.x;     // over NB*NS*NE/8
    float4 a = x[2*i], b = x[2*i+1];
    uint4 o;
    o.x = packh2(a.x, a.y); o.y = packh2(a.z, a.w);
    o.z = packh2(b.x, b.y); o.w = packh2(b.z, b.w);
    ((uint4*)g_x)[i] = o;
}

// ---------------------------------------------------------------------------
// Cache copy: fp32 -> fp16; K straight, V transposed via smem tile.
// ---------------------------------------------------------------------------
__global__ __launch_bounds__(256) void copy_cache_kernel(
    const float4* __restrict__ kc, const float4* __restrict__ vc)
{
    __shared__ __half sh[64*68];
    const int b = blockIdx.y, l0 = blockIdx.x*64, t = threadIdx.x;
    const int lr = t>>2, d0 = (t&3)*16;
    const int l = l0 + lr;
    const float4* krow = kc + ((size_t)(b*NOLD + l)*64 + d0)/4;
    const float4* vrow = vc + ((size_t)(b*NOLD + l)*64 + d0)/4;
    uint32_t* kd = (uint32_t*)(g_k + (size_t)(b*NL + l)*64 + d0);
#pragma unroll
    for (int i = 0; i < 4; i++) {
        float4 kv = krow[i];
        kd[i*2]   = packh2(kv.x, kv.y);
        kd[i*2+1] = packh2(kv.z, kv.w);
        float4 vv = vrow[i];
        uint32_t* sd = (uint32_t*)&sh[lr*68 + d0 + i*4];
        sd[0] = packh2(vv.x, vv.y);
        sd[1] = packh2(vv.z, vv.w);
    }
    __syncthreads();
    const int d = t>>2, q = t&3;
    uint32_t ob[8];
#pragma unroll
    for (int j = 0; j < 8; j++) {
        __half2 hh = __halves2half2(sh[(q*16+2*j)*68 + d], sh[(q*16+2*j+1)*68 + d]);
        ob[j] = *(uint32_t*)&hh;
    }
    uint32_t* vd = (uint32_t*)(g_v + (size_t)(b*NDH + d)*NL + l0 + q*16);
#pragma unroll
    for (int j = 0; j < 8; j++) vd[j] = ob[j];
}

// ---------------------------------------------------------------------------
// fp16 GEMM core: 32x64 tile, K=512 in 32-k slabs, double buffered.
// ---------------------------------------------------------------------------
#define HSTR 40
#define AH_ST (32*HSTR)
#define WH_ST (64*HSTR)

__device__ __forceinline__ void gemm_f16_core(
    const __half* __restrict__ A, const float* __restrict__ W,
    int m0, int n0, __half* Ah, __half* Wh, float acc[2][4])
{
    const int t = threadIdx.x;
    const int lane = t & 31, g = lane >> 2, tg = lane & 3;
    const int warp = t >> 5, wm = warp >> 2, wn = warp & 3;
    const int arow = t >> 3, acol = (t & 7) * 4;
    const int wrow = t >> 2, wcol = (t & 3) * 8;

#pragma unroll
    for (int nt = 0; nt < 2; nt++)
#pragma unroll
        for (int i = 0; i < 4; i++) acc[nt][i] = 0.f;

    uint2 ra = *(const uint2*)(A + (size_t)(m0+arow)*NE + acol);
    float4 rw0 = *(const float4*)(W + (size_t)(n0+wrow)*NE + wcol);
    float4 rw1 = *(const float4*)(W + (size_t)(n0+wrow)*NE + wcol + 4);
    {
        *(uint2*)&Ah[arow*HSTR + acol] = ra;
        uint4 wv;
        wv.x = packh2(rw0.x, rw0.y); wv.y = packh2(rw0.z, rw0.w);
        wv.z = packh2(rw1.x, rw1.y); wv.w = packh2(rw1.z, rw1.w);
        *(uint4*)&Wh[wrow*HSTR + wcol] = wv;
    }
    __syncthreads();

    for (int s = 0; s < 16; s++) {
        int p = s & 1;
        if (s < 15) {
            int k0 = (s+1)*32;
            ra  = *(const uint2*)(A + (size_t)(m0+arow)*NE + k0 + acol);
            rw0 = *(const float4*)(W + (size_t)(n0+wrow)*NE + k0 + wcol);
            rw1 = *(const float4*)(W + (size_t)(n0+wrow)*NE + k0 + wcol + 4);
        }
        const __half* Ap = Ah + p*AH_ST;
        const __half* Wp = Wh + p*WH_ST;
#pragma unroll
        for (int kt = 0; kt < 2; kt++) {
            uint32_t a[4];
            const __half* ab = Ap + (wm*16)*HSTR + kt*16;
            a[0] = *(const uint32_t*)&ab[g*HSTR + 2*tg];
            a[1] = *(const uint32_t*)&ab[(g+8)*HSTR + 2*tg];
            a[2] = *(const uint32_t*)&ab[g*HSTR + 2*tg + 8];
            a[3] = *(const uint32_t*)&ab[(g+8)*HSTR + 2*tg + 8];
#pragma unroll
            for (int nt = 0; nt < 2; nt++) {
                const __half* wb = Wp + (wn*16 + nt*8 + g)*HSTR + kt*16;
                uint32_t bb[2];
                bb[0] = *(const uint32_t*)&wb[2*tg];
                bb[1] = *(const uint32_t*)&wb[2*tg + 8];
                mma_f16(acc[nt], a, bb);
            }
        }
        if (s < 15) {
            *(uint2*)&Ah[(1-p)*AH_ST + arow*HSTR + acol] = ra;
            uint4 wv;
            wv.x = packh2(rw0.x, rw0.y); wv.y = packh2(rw0.z, rw0.w);
            wv.z = packh2(rw1.x, rw1.y); wv.w = packh2(rw1.z, rw1.w);
            *(uint4*)&Wh[(1-p)*WH_ST + wrow*HSTR + wcol] = wv;
        }
        __syncthreads();
    }
}

__global__ __launch_bounds__(256) void qkv_tc_kernel(
    const float* __restrict__ Wq, const float* __restrict__ bq,
    const float* __restrict__ Wk, const float* __restrict__ bk,
    const float* __restrict__ Wv, const float* __restrict__ bv)
{
    __shared__ __half Ah[2*AH_ST];
    __shared__ __half Wh[2*WH_ST];
    const int mode = blockIdx.z;
    const float* W    = (mode == 0) ? Wq : ((mode == 1) ? Wk : Wv);
    const float* bias = (mode == 0) ? bq : ((mode == 1) ? bk : bv);
    const int m0 = blockIdx.y*32, n0 = blockIdx.x*64;

    float acc[2][4];
    gemm_f16_core(g_x, W, m0, n0, Ah, Wh, acc);

    const int lane = threadIdx.x & 31, g = lane >> 2, tg = lane & 3;
    const int warp = threadIdx.x >> 5, wm = warp >> 2, wn = warp & 3;
    const float QSCALE = 0.125f * 1.44269504088896f;   // 1/sqrt(64) * log2(e)
#pragma unroll
    for (int nt = 0; nt < 2; nt++) {
#pragma unroll
        for (int i = 0; i < 4; i++) {
            int m = m0 + wm*16 + g + (i >= 2 ? 8 : 0);
            int n = n0 + wn*16 + nt*8 + 2*tg + (i & 1);
            float v = acc[nt][i] + bias[n];
            int b = m >> 8, s = m & 255;
            int hh = n >> 6, d = n & 63;
            int l = NOLD + s*NH + hh;
            if (mode == 0)      g_q[m*NE + n] = __float2half_rn(v * QSCALE);
            else if (mode == 1) g_k[(size_t)(b*NL + l)*NDH + d] = __float2half_rn(v);
            else                g_v[(size_t)(b*NDH + d)*NL + l] = __float2half_rn(v);
        }
    }
}

__global__ __launch_bounds__(256) void out_tc_kernel(
    const float* __restrict__ Wo, const float* __restrict__ bo,
    float* __restrict__ out)
{
    __shared__ __half Ah[2*AH_ST];
    __shared__ __half Wh[2*WH_ST];
    const int m0 = blockIdx.y*32, n0 = blockIdx.x*64;
    float acc[2][4];
    gemm_f16_core(g_attn_h, Wo, m0, n0, Ah, Wh, acc);

    const int lane = threadIdx.x & 31, g = lane >> 2, tg = lane & 3;
    const int warp = threadIdx.x >> 5, wm = warp >> 2, wn = warp & 3;
#pragma unroll
    for (int nt = 0; nt < 2; nt++) {
        int r0 = m0 + wm*16 + g;
        int c  = n0 + wn*16 + nt*8 + 2*tg;
        *(float2*)(out + (size_t)r0*NE + c) =
            make_float2(acc[nt][0] + bo[c], acc[nt][1] + bo[c+1]);
        *(float2*)(out + (size_t)(r0+8)*NE + c) =
            make_float2(acc[nt][2] + bo[c], acc[nt][3] + bo[c+1]);
    }
}

// ---------------------------------------------------------------------------
// fp16 flash attention, register softmax via ex2.f16x2 (fixed max), split-L x4.
// Block = (32 q, h, b*4+lh); 256 threads (8 warps: wm in {0,1} x wn in {0..3}).
// Warp-pair (wm0,wm1 sharing wn) owns key strip [wn*32, wn*32+32) of each
// 128-key chunk: stages it (cp.async), QKs it, PVs it. Loop needs only a
// named 64-thread pair barrier per chunk — no block-wide sync.
// smem: Qs[32][72] | Ks 2x[128][72] | Vt 2x[64][136] (halves) = 76288 B.
// ---------------------------------------------------------------------------
#define FLASH_SMEM 76288
#define KS_BYTES (128*72*2)
#define VT_BYTES (64*136*2)

__global__ __launch_bounds__(256, 2) void flash_f16_kernel()
{
    extern __shared__ __half smh[];
    __half* Qs = smh;                   // [32][72]
    __half* Ks = smh + 2304;            // 2 x [128][72]
    __half* Vt = smh + 20736;           // 2 x [64][136]
    float* red  = (float*)(smh + 2304); // epilogue reuse: [4][32][64]
    float* lred = red + 4*32*64;        // [4][32]

    const int t = threadIdx.x;
    const int lane = t & 31, g = lane>>2, tg = lane&3;
    const int warp = t>>5, wm = warp>>2, wn = warp&3;
    const int tp = wm*32 + lane;        // 0..63 within pair
    const int bz = blockIdx.z, b = bz>>2, lh = bz&3;
    const int h = blockIdx.y, q0 = blockIdx.x*32;

    {   // load Q tile (prescaled fp16, log2-domain)
        int q = t>>3, oct = t&7;
        *(uint4*)&Qs[q*72 + oct*8] =
            *((const uint4*)g_q + (size_t)((b*NS + q0 + q)*NE + h*64)/8 + oct);
    }

    const __half* kg = g_k + (size_t)b*NL*64;
    const __half* vg = g_v + (size_t)b*64*NL;
    const int l0base = lh*NCH2*FKT;

    // pair-local staging assignment
    const int krow = wn*32 + (tp>>1);          // key row this thread stages
    const int khb  = tp&1;                     // which 32-dim half
    uint32_t ks_dst = (uint32_t)__cvta_generic_to_shared(&Ks[krow*72 + khb*32]);
    uint32_t vt_dst = (uint32_t)__cvta_generic_to_shared(&Vt[tp*136 + wn*32]);
    const __half* ksrc = kg + (size_t)krow*64 + khb*32;   // + l0*64
    const __half* vsrc = vg + (size_t)tp*NL + wn*32;      // + l0

    {   // prologue: chunk 0 -> buffers[0]
        const __half* ks0 = ksrc + (size_t)l0base*64;
        const __half* vs0 = vsrc + l0base;
#pragma unroll
        for (int i = 0; i < 4; i++) { CP16(ks_dst + i*16, ks0 + i*8); }
#pragma unroll
        for (int i = 0; i < 4; i++) { CP16(vt_dst + i*16, vs0 + i*8); }
        CP_COMMIT(); CP_WAIT0();
    }
    __syncthreads();   // also publishes Qs

    // hoist Q fragments
    uint32_t qa[4][4];
#pragma unroll
    for (int kt = 0; kt < 4; kt++) {
        const __half* base = Qs + (wm*16)*72 + kt*16;
        qa[kt][0] = *(const uint32_t*)&base[g*72 + 2*tg];
        qa[kt][1] = *(const uint32_t*)&base[(g+8)*72 + 2*tg];
        qa[kt][2] = *(const uint32_t*)&base[g*72 + 2*tg + 8];
        qa[kt][3] = *(const uint32_t*)&base[(g+8)*72 + 2*tg + 8];
    }

    float o[8][4];
#pragma unroll
    for (int nd = 0; nd < 8; nd++)
#pragma unroll
        for (int i = 0; i < 4; i++) o[nd][i] = 0.f;
    float lp0 = 0.f, lp1 = 0.f;
    const int barid = 1 + wn;

    for (int ch = 0; ch < NCH2; ch++) {
        const int p = ch & 1;
        if (ch + 1 < NCH2) {   // cp.async next chunk into buffers[1-p]
            int l0 = l0base + (ch+1)*FKT;
            uint32_t kd = ks_dst + (1-p)*KS_BYTES;
            uint32_t vd = vt_dst + (1-p)*VT_BYTES;
            const __half* ks2 = ksrc + (size_t)l0*64;
            const __half* vs2 = vsrc + l0;
#pragma unroll
            for (int i = 0; i < 4; i++) { CP16(kd + i*16, ks2 + i*8); }
#pragma unroll
            for (int i = 0; i < 4; i++) { CP16(vd + i*16, vs2 + i*8); }
        }
        CP_COMMIT();

        // ---- QK: warp's 32-key strip ----
        const __half* Kp = Ks + p*(128*72);
        float sc[4][4];
#pragma unroll
        for (int nt = 0; nt < 4; nt++)
#pragma unroll
            for (int i = 0; i < 4; i++) sc[nt][i] = 0.f;
#pragma unroll
        for (int kt = 0; kt < 4; kt++) {
#pragma unroll
            for (int nt = 0; nt < 4; nt++) {
                const __half* kb2 = Kp + (wn*32 + nt*8 + g)*72 + kt*16;
                uint32_t bb[2];
                bb[0] = *(const uint32_t*)&kb2[2*tg];
                bb[1] = *(const uint32_t*)&kb2[2*tg + 8];
                mma_f16(sc[nt], qa[kt], bb);
            }
        }

        // ---- P = 2^S via ex2.f16x2; accum layout == A-frag layout ----
        uint32_t pa[2][4];
#pragma unroll
        for (int j = 0; j < 2; j++) {
            pa[j][0] = ex2h2(packh2(sc[2*j][0],   sc[2*j][1]));
            pa[j][1] = ex2h2(packh2(sc[2*j][2],   sc[2*j][3]));
            pa[j][2] = ex2h2(packh2(sc[2*j+1][0], sc[2*j+1][1]));
            pa[j][3] = ex2h2(packh2(sc[2*j+1][2], sc[2*j+1][3]));
        }
        {   // l accumulation from the same fp16 P values
            __half2 hg = __hadd2(
                __hadd2(*(__half2*)&pa[0][0], *(__half2*)&pa[0][2]),
                __hadd2(*(__half2*)&pa[1][0], *(__half2*)&pa[1][2]));
            __half2 h8 = __hadd2(
                __hadd2(*(__half2*)&pa[0][1], *(__half2*)&pa[0][3]),
                __hadd2(*(__half2*)&pa[1][1], *(__half2*)&pa[1][3]));
            lp0 += __low2float(hg) + __high2float(hg);
            lp1 += __low2float(h8) + __high2float(h8);
        }

        // ---- partial PV over this warp's strip, all 64 dims ----
        const __half* Vp = Vt + p*(64*136);
#pragma unroll
        for (int j = 0; j < 2; j++) {
            const int kc = wn*32 + j*16;
#pragma unroll
            for (int nd = 0; nd < 8; nd++) {
                const __half* vb2 = Vp + (nd*8 + g)*136 + kc + 2*tg;
                uint32_t bb[2];
                bb[0] = *(const uint32_t*)vb2;
                bb[1] = *(const uint32_t*)(vb2 + 8);
                mma_f16(o[nd], pa[j], bb);
            }
        }

        CP_WAIT0();
        asm volatile("bar.sync %0, 64;" :: "r"(barid) : "memory");
    }

    __syncthreads();   // all pairs done before reusing smem as `red`

    // ---- epilogue: cross-warp O reduction ----
#pragma unroll
    for (int nd = 0; nd < 8; nd++) {
        float* r0 = &red[(size_t)(wn*32 + wm*16 + g)*64 + nd*8 + 2*tg];
        r0[0] = o[nd][0]; r0[1] = o[nd][1];
        float* r1 = r0 + 8*64;
        r1[0] = o[nd][2]; r1[1] = o[nd][3];
    }
    lp0 += __shfl_xor_sync(0xffffffffu, lp0, 1);
    lp0 += __shfl_xor_sync(0xffffffffu, lp0, 2);
    lp1 += __shfl_xor_sync(0xffffffffu, lp1, 1);
    lp1 += __shfl_xor_sync(0xffffffffu, lp1, 2);
    if (tg == 0) {
        lred[wn*32 + wm*16 + g]     = lp0;
        lred[wn*32 + wm*16 + g + 8] = lp1;
    }
    __syncthreads();

    {
        int row = t>>3, dc = (t&7)*8;
        float4 s0 = *(const float4*)&red[(size_t)row*64 + dc];
        float4 s1 = *(const float4*)&red[(size_t)row*64 + dc + 4];
#pragma unroll
        for (int w = 1; w < 4; w++) {
            const float* rr = &red[(size_t)(w*32 + row)*64 + dc];
            float4 a0 = *(const float4*)rr;
            float4 a1 = *(const float4*)(rr + 4);
            s0.x += a0.x; s0.y += a0.y; s0.z += a0.z; s0.w += a0.w;
            s1.x += a1.x; s1.y += a1.y; s1.z += a1.z; s1.w += a1.w;
        }
        float* po = g_po + (size_t)lh*(NB*NS*NE) +
                    (size_t)(b*NS + q0 + row)*NE + h*64 + dc;
        *(float4*)po       = s0;
        *(float4*)(po + 4) = s1;
    }
    if (t < 32)
        g_pl[lh*(NB*NH*NS) + (b*NH + h)*NS + q0 + t] =
            lred[t] + lred[32 + t] + lred[64 + t] + lred[96 + t];
}

// ---------------------------------------------------------------------------
// Merge 4 partials: attn = sum(O_s) / sum(l_s), stored fp16 for out-proj.
// ---------------------------------------------------------------------------
__global__ void merge_kernel()
{
    int i = blockIdx.x*blockDim.x + threadIdx.x;    // over NB*NS*NE/4
    if (i >= NB*NS*NE/4) return;
    int dq = i & 15;
    int h  = (i >> 4) & 7;
    int q  = (i >> 7) & 255;
    int b  = i >> 15;
    int rml = (b*NH + h)*NS + q;
    float lsum = 0.f;
#pragma unroll
    for (int s = 0; s < FSPLIT; s++) lsum += g_pl[s*(NB*NH*NS) + rml];
    float inv = 1.f / lsum;
    int off4 = ((b*NS + q)*NE + h*NDH + dq*4) >> 2;
    float4 acc = make_float4(0.f, 0.f, 0.f, 0.f);
#pragma unroll
    for (int s = 0; s < FSPLIT; s++) {
        float4 ov = ((const float4*)(g_po + (size_t)s*NB*NS*NE))[off4];
        acc.x += ov.x; acc.y += ov.y; acc.z += ov.z; acc.w += ov.w;
    }
    uint2 r;
    r.x = packh2(acc.x*inv, acc.y*inv);
    r.y = packh2(acc.z*inv, acc.w*inv);
    ((uint2*)g_attn_h)[off4] = r;
}

// ---------------------------------------------------------------------------
extern "C" void kernel_launch(void* const* d_in, const int* in_sizes, int n_in,
                              void* d_out, int out_size)
{
    const float* x  = (const float*)d_in[0];
    const float* kc = (const float*)d_in[1];
    const float* vc = (const float*)d_in[2];
    const float* Wq = (const float*)d_in[3];
    const float* bq = (const float*)d_in[4];
    const float* Wk = (const float*)d_in[5];
    const float* bk = (const float*)d_in[6];
    const float* Wv = (const float*)d_in[7];
    const float* bv = (const float*)d_in[8];
    const float* Wo = (const float*)d_in[9];
    const float* bo = (const float*)d_in[10];
    float* out = (float*)d_out;

    cudaFuncSetAttribute(flash_f16_kernel,
                         cudaFuncAttributeMaxDynamicSharedMemorySize,
                         FLASH_SMEM);

    convert_x_kernel<<<NB*NS*NE/8/256, 256>>>((const float4*)x);

    copy_cache_kernel<<<dim3(NOLD/64, NB), 256>>>(
        (const float4*)kc, (const float4*)vc);

    qkv_tc_kernel<<<dim3(8, 16, 3), 256>>>(Wq, bq, Wk, bk, Wv, bv);

    flash_f16_kernel<<<dim3(NS/32, NH, NB*FSPLIT), 256, FLASH_SMEM>>>();

    merge_kernel<<<(NB*NS*NE/4 + 255)/256, 256>>>();

    out_tc_kernel<<<dim3(8, 16), 256>>>(Wo, bo, out);
}

// round 8
// speedup vs baseline: 1.3069x; 1.3069x over previous
#include <cuda_runtime.h>
#include <cuda_fp16.h>
#include <cstdint>

#define NB 2
#define NS 256
#define NE 512
#define NH 8
#define NDH 64
#define NTC 768
#define NL 8192
#define NOLD 6144
#define FSPLIT 4
#define FKT 128
#define NCH2 (NL/FKT/FSPLIT)   // 16 chunks per flash block

// Scratch (device globals)
__device__ __half g_x[NB*NS*NE];        // x in fp16
__device__ __half g_q[NB*NS*NE];        // Q proj (scaled by 0.125*log2e)
__device__ __half g_k[NB*NL*NDH];       // concat K        [b][l][d]
__device__ __half g_v[NB*NDH*NL];       // concat V TRANSPOSED [b][d][l]
__device__ __half g_attn_h[NB*NS*NE];   // merged attention (fp16)
__device__ float  g_po[FSPLIT*NB*NS*NE];
__device__ float  g_pl[FSPLIT*NB*NH*NS];

// ---------------------------------------------------------------------------
__device__ __forceinline__ void mma_f16(float c[4], const uint32_t a[4],
                                        const uint32_t b[2]) {
    asm volatile(
        "mma.sync.aligned.m16n8k16.row.col.f32.f16.f16.f32 "
        "{%0,%1,%2,%3}, {%4,%5,%6,%7}, {%8,%9}, {%0,%1,%2,%3};"
        : "+f"(c[0]), "+f"(c[1]), "+f"(c[2]), "+f"(c[3])
        : "r"(a[0]), "r"(a[1]), "r"(a[2]), "r"(a[3]), "r"(b[0]), "r"(b[1]));
}
__device__ __forceinline__ uint32_t packh2(float x, float y) {
    __half2 h = __floats2half2_rn(x, y);
    return *(uint32_t*)&h;
}
__device__ __forceinline__ float ex2f(float x) {
    float r;
    asm("ex2.approx.f32 %0, %1;" : "=f"(r) : "f"(x));
    return r;
}
#define CP16(d, s) asm volatile("cp.async.cg.shared.global [%0], [%1], 16;" \
                                :: "r"(d), "l"(s))
#define CP_COMMIT() asm volatile("cp.async.commit_group;")
#define CP_WAIT0()  asm volatile("cp.async.wait_group 0;")

// ---------------------------------------------------------------------------
// x -> fp16
__global__ __launch_bounds__(256) void convert_x_kernel(const float4* __restrict__ x)
{
    int i = blockIdx.x*256 + threadIdx.x;     // over NB*NS*NE/8
    float4 a = x[2*i], b = x[2*i+1];
    uint4 o;
    o.x = packh2(a.x, a.y); o.y = packh2(a.z, a.w);
    o.z = packh2(b.x, b.y); o.w = packh2(b.z, b.w);
    ((uint4*)g_x)[i] = o;
}

// ---------------------------------------------------------------------------
// Cache copy: fp32 -> fp16; K straight, V transposed via smem tile.
// ---------------------------------------------------------------------------
__global__ __launch_bounds__(256) void copy_cache_kernel(
    const float4* __restrict__ kc, const float4* __restrict__ vc)
{
    __shared__ __half sh[64*68];
    const int b = blockIdx.y, l0 = blockIdx.x*64, t = threadIdx.x;
    const int lr = t>>2, d0 = (t&3)*16;
    const int l = l0 + lr;
    const float4* krow = kc + ((size_t)(b*NOLD + l)*64 + d0)/4;
    const float4* vrow = vc + ((size_t)(b*NOLD + l)*64 + d0)/4;
    uint32_t* kd = (uint32_t*)(g_k + (size_t)(b*NL + l)*64 + d0);
#pragma unroll
    for (int i = 0; i < 4; i++) {
        float4 kv = krow[i];
        kd[i*2]   = packh2(kv.x, kv.y);
        kd[i*2+1] = packh2(kv.z, kv.w);
        float4 vv = vrow[i];
        uint32_t* sd = (uint32_t*)&sh[lr*68 + d0 + i*4];
        sd[0] = packh2(vv.x, vv.y);
        sd[1] = packh2(vv.z, vv.w);
    }
    __syncthreads();
    const int d = t>>2, q = t&3;
    uint32_t ob[8];
#pragma unroll
    for (int j = 0; j < 8; j++) {
        __half2 hh = __halves2half2(sh[(q*16+2*j)*68 + d], sh[(q*16+2*j+1)*68 + d]);
        ob[j] = *(uint32_t*)&hh;
    }
    uint32_t* vd = (uint32_t*)(g_v + (size_t)(b*NDH + d)*NL + l0 + q*16);
#pragma unroll
    for (int j = 0; j < 8; j++) vd[j] = ob[j];
}

// ---------------------------------------------------------------------------
// fp16 GEMM core: 32x64 tile, K=512 in 32-k slabs, double buffered.
// ---------------------------------------------------------------------------
#define HSTR 40
#define AH_ST (32*HSTR)
#define WH_ST (64*HSTR)

__device__ __forceinline__ void gemm_f16_core(
    const __half* __restrict__ A, const float* __restrict__ W,
    int m0, int n0, __half* Ah, __half* Wh, float acc[2][4])
{
    const int t = threadIdx.x;
    const int lane = t & 31, g = lane >> 2, tg = lane & 3;
    const int warp = t >> 5, wm = warp >> 2, wn = warp & 3;
    const int arow = t >> 3, acol = (t & 7) * 4;
    const int wrow = t >> 2, wcol = (t & 3) * 8;

#pragma unroll
    for (int nt = 0; nt < 2; nt++)
#pragma unroll
        for (int i = 0; i < 4; i++) acc[nt][i] = 0.f;

    uint2 ra = *(const uint2*)(A + (size_t)(m0+arow)*NE + acol);
    float4 rw0 = *(const float4*)(W + (size_t)(n0+wrow)*NE + wcol);
    float4 rw1 = *(const float4*)(W + (size_t)(n0+wrow)*NE + wcol + 4);
    {
        *(uint2*)&Ah[arow*HSTR + acol] = ra;
        uint4 wv;
        wv.x = packh2(rw0.x, rw0.y); wv.y = packh2(rw0.z, rw0.w);
        wv.z = packh2(rw1.x, rw1.y); wv.w = packh2(rw1.z, rw1.w);
        *(uint4*)&Wh[wrow*HSTR + wcol] = wv;
    }
    __syncthreads();

    for (int s = 0; s < 16; s++) {
        int p = s & 1;
        if (s < 15) {
            int k0 = (s+1)*32;
            ra  = *(const uint2*)(A + (size_t)(m0+arow)*NE + k0 + acol);
            rw0 = *(const float4*)(W + (size_t)(n0+wrow)*NE + k0 + wcol);
            rw1 = *(const float4*)(W + (size_t)(n0+wrow)*NE + k0 + wcol + 4);
        }
        const __half* Ap = Ah + p*AH_ST;
        const __half* Wp = Wh + p*WH_ST;
#pragma unroll
        for (int kt = 0; kt < 2; kt++) {
            uint32_t a[4];
            const __half* ab = Ap + (wm*16)*HSTR + kt*16;
            a[0] = *(const uint32_t*)&ab[g*HSTR + 2*tg];
            a[1] = *(const uint32_t*)&ab[(g+8)*HSTR + 2*tg];
            a[2] = *(const uint32_t*)&ab[g*HSTR + 2*tg + 8];
            a[3] = *(const uint32_t*)&ab[(g+8)*HSTR + 2*tg + 8];
#pragma unroll
            for (int nt = 0; nt < 2; nt++) {
                const __half* wb = Wp + (wn*16 + nt*8 + g)*HSTR + kt*16;
                uint32_t bb[2];
                bb[0] = *(const uint32_t*)&wb[2*tg];
                bb[1] = *(const uint32_t*)&wb[2*tg + 8];
                mma_f16(acc[nt], a, bb);
            }
        }
        if (s < 15) {
            *(uint2*)&Ah[(1-p)*AH_ST + arow*HSTR + acol] = ra;
            uint4 wv;
            wv.x = packh2(rw0.x, rw0.y); wv.y = packh2(rw0.z, rw0.w);
            wv.z = packh2(rw1.x, rw1.y); wv.w = packh2(rw1.z, rw1.w);
            *(uint4*)&Wh[(1-p)*WH_ST + wrow*HSTR + wcol] = wv;
        }
        __syncthreads();
    }
}

__global__ __launch_bounds__(256) void qkv_tc_kernel(
    const float* __restrict__ Wq, const float* __restrict__ bq,
    const float* __restrict__ Wk, const float* __restrict__ bk,
    const float* __restrict__ Wv, const float* __restrict__ bv)
{
    __shared__ __half Ah[2*AH_ST];
    __shared__ __half Wh[2*WH_ST];
    const int mode = blockIdx.z;
    const float* W    = (mode == 0) ? Wq : ((mode == 1) ? Wk : Wv);
    const float* bias = (mode == 0) ? bq : ((mode == 1) ? bk : bv);
    const int m0 = blockIdx.y*32, n0 = blockIdx.x*64;

    float acc[2][4];
    gemm_f16_core(g_x, W, m0, n0, Ah, Wh, acc);

    const int lane = threadIdx.x & 31, g = lane >> 2, tg = lane & 3;
    const int warp = threadIdx.x >> 5, wm = warp >> 2, wn = warp & 3;
    const float QSCALE = 0.125f * 1.44269504088896f;   // 1/sqrt(64) * log2(e)
#pragma unroll
    for (int nt = 0; nt < 2; nt++) {
#pragma unroll
        for (int i = 0; i < 4; i++) {
            int m = m0 + wm*16 + g + (i >= 2 ? 8 : 0);
            int n = n0 + wn*16 + nt*8 + 2*tg + (i & 1);
            float v = acc[nt][i] + bias[n];
            int b = m >> 8, s = m & 255;
            int hh = n >> 6, d = n & 63;
            int l = NOLD + s*NH + hh;
            if (mode == 0)      g_q[m*NE + n] = __float2half_rn(v * QSCALE);
            else if (mode == 1) g_k[(size_t)(b*NL + l)*NDH + d] = __float2half_rn(v);
            else                g_v[(size_t)(b*NDH + d)*NL + l] = __float2half_rn(v);
        }
    }
}

__global__ __launch_bounds__(256) void out_tc_kernel(
    const float* __restrict__ Wo, const float* __restrict__ bo,
    float* __restrict__ out)
{
    __shared__ __half Ah[2*AH_ST];
    __shared__ __half Wh[2*WH_ST];
    const int m0 = blockIdx.y*32, n0 = blockIdx.x*64;
    float acc[2][4];
    gemm_f16_core(g_attn_h, Wo, m0, n0, Ah, Wh, acc);

    const int lane = threadIdx.x & 31, g = lane >> 2, tg = lane & 3;
    const int warp = threadIdx.x >> 5, wm = warp >> 2, wn = warp & 3;
#pragma unroll
    for (int nt = 0; nt < 2; nt++) {
        int r0 = m0 + wm*16 + g;
        int c  = n0 + wn*16 + nt*8 + 2*tg;
        *(float2*)(out + (size_t)r0*NE + c) =
            make_float2(acc[nt][0] + bo[c], acc[nt][1] + bo[c+1]);
        *(float2*)(out + (size_t)(r0+8)*NE + c) =
            make_float2(acc[nt][2] + bo[c], acc[nt][3] + bo[c+1]);
    }
}

// ---------------------------------------------------------------------------
// fp16 flash attention, QT=64, register softmax via ex2.approx.f32 (fixed
// max, log2-domain Q), split-L x4.
// Block = (64 q, h, b*4+lh); 256 threads, 8 warps = 4m x 2n.
// Warp (wm, wn): 16 q-rows (wm*16) x 64-key strip (wn*64) per 128-key chunk:
//   QK 32 mma -> exp in regs (accum layout == A-frag layout) -> PV 32 mma
//   (partial O over its strip, all 64 dims). Cross-wn O reduction once at end.
// smem halves: Qs[64][72] | Ks 2x[128][72] | Vt 2x[64][136] = 80896 B.
// 1 __syncthreads per chunk; cp.async double-buffered staging.
// ---------------------------------------------------------------------------
#define FLASH_SMEM 80896
#define QS_H  (64*72)
#define KS_H  (128*72)
#define VT_H  (64*136)

__global__ __launch_bounds__(256, 2) void flash_f16_kernel()
{
    extern __shared__ __half smh[];
    __half* Qs = smh;                    // [64][72]
    __half* Ks = smh + QS_H;             // 2 x [128][72]
    __half* Vt = smh + QS_H + 2*KS_H;    // 2 x [64][136]
    float* red  = (float*)(smh + QS_H);  // epilogue reuse: [2][64][64]
    float* lred = red + 2*64*64;         // [2][64]

    const int t = threadIdx.x;
    const int lane = t & 31, g = lane>>2, tg = lane&3;
    const int warp = t>>5, wm = warp>>1, wn = warp&1;
    const int bz = blockIdx.z, b = bz>>2, lh = bz&3;
    const int h = blockIdx.y, q0 = blockIdx.x*64;

    {   // load Q tile (prescaled fp16, log2-domain): 64x64 halves
        int q = t>>2, oct = t&3;
        const uint4* src = (const uint4*)g_q +
            (size_t)((b*NS + q0 + q)*NE + h*64)/8 + oct*2;
        *(uint4*)&Qs[q*72 + oct*16]     = src[0];
        *(uint4*)&Qs[q*72 + oct*16 + 8] = src[1];
    }

    const __half* kg = g_k + (size_t)b*NL*64;
    const __half* vg = g_v + (size_t)b*64*NL;
    const int l0base = lh*NCH2*FKT;
    const int krow = t>>1, khb = t&1;
    const int vrow = t>>2, vq = t&3;
    uint32_t ks_dst = (uint32_t)__cvta_generic_to_shared(&Ks[krow*72 + khb*32]);
    uint32_t vt_dst = (uint32_t)__cvta_generic_to_shared(&Vt[vrow*136 + vq*32]);
    const __half* ksrc = kg + (size_t)krow*64 + khb*32;   // + l0*64
    const __half* vsrc = vg + (size_t)vrow*NL + vq*32;    // + l0

    {   // prologue: chunk 0 -> buffers[0]
        const __half* ks0 = ksrc + (size_t)l0base*64;
        const __half* vs0 = vsrc + l0base;
#pragma unroll
        for (int i = 0; i < 4; i++) { CP16(ks_dst + i*16, ks0 + i*8); }
#pragma unroll
        for (int i = 0; i < 4; i++) { CP16(vt_dst + i*16, vs0 + i*8); }
        CP_COMMIT(); CP_WAIT0();
    }
    __syncthreads();   // also publishes Qs

    // hoist Q fragments (warp's 16 rows)
    uint32_t qa[4][4];
#pragma unroll
    for (int kt = 0; kt < 4; kt++) {
        const __half* base = Qs + (wm*16)*72 + kt*16;
        qa[kt][0] = *(const uint32_t*)&base[g*72 + 2*tg];
        qa[kt][1] = *(const uint32_t*)&base[(g+8)*72 + 2*tg];
        qa[kt][2] = *(const uint32_t*)&base[g*72 + 2*tg + 8];
        qa[kt][3] = *(const uint32_t*)&base[(g+8)*72 + 2*tg + 8];
    }

    float o[8][4];
#pragma unroll
    for (int nd = 0; nd < 8; nd++)
#pragma unroll
        for (int i = 0; i < 4; i++) o[nd][i] = 0.f;
    float lp0 = 0.f, lp1 = 0.f;

    for (int ch = 0; ch < NCH2; ch++) {
        const int p = ch & 1;
        if (ch + 1 < NCH2) {   // cp.async next chunk into buffers[1-p]
            int l0 = l0base + (ch+1)*FKT;
            uint32_t kd = ks_dst + (1-p)*(KS_H*2);
            uint32_t vd = vt_dst + (1-p)*(VT_H*2);
            const __half* ks2 = ksrc + (size_t)l0*64;
            const __half* vs2 = vsrc + l0;
#pragma unroll
            for (int i = 0; i < 4; i++) { CP16(kd + i*16, ks2 + i*8); }
#pragma unroll
            for (int i = 0; i < 4; i++) { CP16(vd + i*16, vs2 + i*8); }
        }
        CP_COMMIT();

        // ---- QK: warp's 16 rows x 64-key strip ----
        const __half* Kp = Ks + p*KS_H;
        float sc[8][4];
#pragma unroll
        for (int nt = 0; nt < 8; nt++)
#pragma unroll
            for (int i = 0; i < 4; i++) sc[nt][i] = 0.f;
#pragma unroll
        for (int kt = 0; kt < 4; kt++) {
#pragma unroll
            for (int nt = 0; nt < 8; nt++) {
                const __half* kb2 = Kp + (wn*64 + nt*8 + g)*72 + kt*16;
                uint32_t bb[2];
                bb[0] = *(const uint32_t*)&kb2[2*tg];
                bb[1] = *(const uint32_t*)&kb2[2*tg + 8];
                mma_f16(sc[nt], qa[kt], bb);
            }
        }

        // ---- P = 2^S (ex2.approx.f32); accum layout == A-frag layout ----
        uint32_t pa[4][4];
#pragma unroll
        for (int j = 0; j < 4; j++) {
            float e00 = ex2f(sc[2*j][0]),   e01 = ex2f(sc[2*j][1]);
            float e02 = ex2f(sc[2*j][2]),   e03 = ex2f(sc[2*j][3]);
            float e10 = ex2f(sc[2*j+1][0]), e11 = ex2f(sc[2*j+1][1]);
            float e12 = ex2f(sc[2*j+1][2]), e13 = ex2f(sc[2*j+1][3]);
            lp0 += e00 + e01 + e10 + e11;   // row wm*16+g
            lp1 += e02 + e03 + e12 + e13;   // row wm*16+g+8
            pa[j][0] = packh2(e00, e01);
            pa[j][1] = packh2(e02, e03);
            pa[j][2] = packh2(e10, e11);
            pa[j][3] = packh2(e12, e13);
        }

        // ---- partial PV over warp's 64-key strip, all 64 dims ----
        const __half* Vp = Vt + p*VT_H;
#pragma unroll
        for (int j = 0; j < 4; j++) {
            const int kc = wn*64 + j*16;
#pragma unroll
            for (int nd = 0; nd < 8; nd++) {
                const __half* vb2 = Vp + (nd*8 + g)*136 + kc + 2*tg;
                uint32_t bb[2];
                bb[0] = *(const uint32_t*)vb2;
                bb[1] = *(const uint32_t*)(vb2 + 8);
                mma_f16(o[nd], pa[j], bb);
            }
        }

        CP_WAIT0();
        __syncthreads();
    }

    // ---- epilogue: cross-wn O reduction (red reuses K/V smem) ----
#pragma unroll
    for (int nd = 0; nd < 8; nd++) {
        float* r0 = &red[(size_t)(wn*64 + wm*16 + g)*64 + nd*8 + 2*tg];
        r0[0] = o[nd][0]; r0[1] = o[nd][1];
        float* r1 = r0 + 8*64;
        r1[0] = o[nd][2]; r1[1] = o[nd][3];
    }
    lp0 += __shfl_xor_sync(0xffffffffu, lp0, 1);
    lp0 += __shfl_xor_sync(0xffffffffu, lp0, 2);
    lp1 += __shfl_xor_sync(0xffffffffu, lp1, 1);
    lp1 += __shfl_xor_sync(0xffffffffu, lp1, 2);
    if (tg == 0) {
        lred[wn*64 + wm*16 + g]     = lp0;
        lred[wn*64 + wm*16 + g + 8] = lp1;
    }
    __syncthreads();

    {
        int row = t>>2, dc = (t&3)*16;
        float4 s[4];
#pragma unroll
        for (int i = 0; i < 4; i++) {
            float4 a0 = *(const float4*)&red[(size_t)row*64 + dc + i*4];
            float4 a1 = *(const float4*)&red[(size_t)(64 + row)*64 + dc + i*4];
            s[i].x = a0.x + a1.x; s[i].y = a0.y + a1.y;
            s[i].z = a0.z + a1.z; s[i].w = a0.w + a1.w;
        }
        float* po = g_po + (size_t)lh*(NB*NS*NE) +
                    (size_t)(b*NS + q0 + row)*NE + h*64 + dc;
#pragma unroll
        for (int i = 0; i < 4; i++) *(float4*)(po + i*4) = s[i];
    }
    if (t < 64)
        g_pl[lh*(NB*NH*NS) + (b*NH + h)*NS + q0 + t] = lred[t] + lred[64 + t];
}

// ---------------------------------------------------------------------------
// Merge 4 partials: attn = sum(O_s) / sum(l_s), stored fp16 for out-proj.
// ---------------------------------------------------------------------------
__global__ void merge_kernel()
{
    int i = blockIdx.x*blockDim.x + threadIdx.x;    // over NB*NS*NE/4
    if (i >= NB*NS*NE/4) return;
    int dq = i & 15;
    int h  = (i >> 4) & 7;
    int q  = (i >> 7) & 255;
    int b  = i >> 15;
    int rml = (b*NH + h)*NS + q;
    float lsum = 0.f;
#pragma unroll
    for (int s = 0; s < FSPLIT; s++) lsum += g_pl[s*(NB*NH*NS) + rml];
    float inv = 1.f / lsum;
    int off4 = ((b*NS + q)*NE + h*NDH + dq*4) >> 2;
    float4 acc = make_float4(0.f, 0.f, 0.f, 0.f);
#pragma unroll
    for (int s = 0; s < FSPLIT; s++) {
        float4 ov = ((const float4*)(g_po + (size_t)s*NB*NS*NE))[off4];
        acc.x += ov.x; acc.y += ov.y; acc.z += ov.z; acc.w += ov.w;
    }
    uint2 r;
    r.x = packh2(acc.x*inv, acc.y*inv);
    r.y = packh2(acc.z*inv, acc.w*inv);
    ((uint2*)g_attn_h)[off4] = r;
}

// ---------------------------------------------------------------------------
extern "C" void kernel_launch(void* const* d_in, const int* in_sizes, int n_in,
                              void* d_out, int out_size)
{
    const float* x  = (const float*)d_in[0];
    const float* kc = (const float*)d_in[1];
    const float* vc = (const float*)d_in[2];
    const float* Wq = (const float*)d_in[3];
    const float* bq = (const float*)d_in[4];
    const float* Wk = (const float*)d_in[5];
    const float* bk = (const float*)d_in[6];
    const float* Wv = (const float*)d_in[7];
    const float* bv = (const float*)d_in[8];
    const float* Wo = (const float*)d_in[9];
    const float* bo = (const float*)d_in[10];
    float* out = (float*)d_out;

    cudaFuncSetAttribute(flash_f16_kernel,
                         cudaFuncAttributeMaxDynamicSharedMemorySize,
                         FLASH_SMEM);

    convert_x_kernel<<<NB*NS*NE/8/256, 256>>>((const float4*)x);

    copy_cache_kernel<<<dim3(NOLD/64, NB), 256>>>(
        (const float4*)kc, (const float4*)vc);

    qkv_tc_kernel<<<dim3(8, 16, 3), 256>>>(Wq, bq, Wk, bk, Wv, bv);

    flash_f16_kernel<<<dim3(NS/64, NH, NB*FSPLIT), 256, FLASH_SMEM>>>();

    merge_kernel<<<(NB*NS*NE/4 + 255)/256, 256>>>();

    out_tc_kernel<<<dim3(8, 16), 256>>>(Wo, bo, out);
}

// round 9
// speedup vs baseline: 1.3108x; 1.0030x over previous
#include <cuda_runtime.h>
#include <cuda_fp16.h>
#include <cstdint>

#define NB 2
#define NS 256
#define NE 512
#define NH 8
#define NDH 64
#define NTC 768
#define NL 8192
#define NOLD 6144
#define FSPLIT 4
#define FKT 128
#define NCH2 (NL/FKT/FSPLIT)   // 16 chunks per flash block

// Scratch (device globals)
__device__ __half g_x[NB*NS*NE];        // x in fp16
__device__ __half g_q[NB*NS*NE];        // Q proj (scaled by 0.125*log2e)
__device__ __half g_k[NB*NL*NDH];       // concat K        [b][l][d]
__device__ __half g_v[NB*NDH*NL];       // concat V TRANSPOSED [b][d][l]
__device__ __half g_attn_h[NB*NS*NE];   // merged attention (fp16)
__device__ float  g_po[FSPLIT*NB*NS*NE];
__device__ float  g_pl[FSPLIT*NB*NH*NS];

// ---------------------------------------------------------------------------
__device__ __forceinline__ void mma_f16(float c[4], const uint32_t a[4],
                                        const uint32_t b[2]) {
    asm volatile(
        "mma.sync.aligned.m16n8k16.row.col.f32.f16.f16.f32 "
        "{%0,%1,%2,%3}, {%4,%5,%6,%7}, {%8,%9}, {%0,%1,%2,%3};"
        : "+f"(c[0]), "+f"(c[1]), "+f"(c[2]), "+f"(c[3])
        : "r"(a[0]), "r"(a[1]), "r"(a[2]), "r"(a[3]), "r"(b[0]), "r"(b[1]));
}
__device__ __forceinline__ uint32_t packh2(float x, float y) {
    __half2 h = __floats2half2_rn(x, y);
    return *(uint32_t*)&h;
}
__device__ __forceinline__ float ex2f(float x) {
    float r;
    asm("ex2.approx.f32 %0, %1;" : "=f"(r) : "f"(x));
    return r;
}
__device__ __forceinline__ void ldsm4(uint32_t r[4], uint32_t a) {
    asm volatile("ldmatrix.sync.aligned.m8n8.x4.shared.b16 {%0,%1,%2,%3}, [%4];"
                 : "=r"(r[0]), "=r"(r[1]), "=r"(r[2]), "=r"(r[3]) : "r"(a));
}
#define CP16(d, s) asm volatile("cp.async.cg.shared.global [%0], [%1], 16;" \
                                :: "r"(d), "l"(s))
#define CP_COMMIT() asm volatile("cp.async.commit_group;")
#define CP_WAIT0()  asm volatile("cp.async.wait_group 0;")

// ---------------------------------------------------------------------------
// x -> fp16
__global__ __launch_bounds__(256) void convert_x_kernel(const float4* __restrict__ x)
{
    int i = blockIdx.x*256 + threadIdx.x;     // over NB*NS*NE/8
    float4 a = x[2*i], b = x[2*i+1];
    uint4 o;
    o.x = packh2(a.x, a.y); o.y = packh2(a.z, a.w);
    o.z = packh2(b.x, b.y); o.w = packh2(b.z, b.w);
    ((uint4*)g_x)[i] = o;
}

// ---------------------------------------------------------------------------
// Cache copy: fp32 -> fp16; K straight, V transposed via smem tile.
// ---------------------------------------------------------------------------
__global__ __launch_bounds__(256) void copy_cache_kernel(
    const float4* __restrict__ kc, const float4* __restrict__ vc)
{
    __shared__ __half sh[64*68];
    const int b = blockIdx.y, l0 = blockIdx.x*64, t = threadIdx.x;
    const int lr = t>>2, d0 = (t&3)*16;
    const int l = l0 + lr;
    const float4* krow = kc + ((size_t)(b*NOLD + l)*64 + d0)/4;
    const float4* vrow = vc + ((size_t)(b*NOLD + l)*64 + d0)/4;
    uint32_t* kd = (uint32_t*)(g_k + (size_t)(b*NL + l)*64 + d0);
#pragma unroll
    for (int i = 0; i < 4; i++) {
        float4 kv = krow[i];
        kd[i*2]   = packh2(kv.x, kv.y);
        kd[i*2+1] = packh2(kv.z, kv.w);
        float4 vv = vrow[i];
        uint32_t* sd = (uint32_t*)&sh[lr*68 + d0 + i*4];
        sd[0] = packh2(vv.x, vv.y);
        sd[1] = packh2(vv.z, vv.w);
    }
    __syncthreads();
    const int d = t>>2, q = t&3;
    uint32_t ob[8];
#pragma unroll
    for (int j = 0; j < 8; j++) {
        __half2 hh = __halves2half2(sh[(q*16+2*j)*68 + d], sh[(q*16+2*j+1)*68 + d]);
        ob[j] = *(uint32_t*)&hh;
    }
    uint32_t* vd = (uint32_t*)(g_v + (size_t)(b*NDH + d)*NL + l0 + q*16);
#pragma unroll
    for (int j = 0; j < 8; j++) vd[j] = ob[j];
}

// ---------------------------------------------------------------------------
// fp16 GEMM core: 32x64 tile, K=512 in 32-k slabs, double buffered.
// ---------------------------------------------------------------------------
#define HSTR 40
#define AH_ST (32*HSTR)
#define WH_ST (64*HSTR)

__device__ __forceinline__ void gemm_f16_core(
    const __half* __restrict__ A, const float* __restrict__ W,
    int m0, int n0, __half* Ah, __half* Wh, float acc[2][4])
{
    const int t = threadIdx.x;
    const int lane = t & 31, g = lane >> 2, tg = lane & 3;
    const int warp = t >> 5, wm = warp >> 2, wn = warp & 3;
    const int arow = t >> 3, acol = (t & 7) * 4;
    const int wrow = t >> 2, wcol = (t & 3) * 8;

#pragma unroll
    for (int nt = 0; nt < 2; nt++)
#pragma unroll
        for (int i = 0; i < 4; i++) acc[nt][i] = 0.f;

    uint2 ra = *(const uint2*)(A + (size_t)(m0+arow)*NE + acol);
    float4 rw0 = *(const float4*)(W + (size_t)(n0+wrow)*NE + wcol);
    float4 rw1 = *(const float4*)(W + (size_t)(n0+wrow)*NE + wcol + 4);
    {
        *(uint2*)&Ah[arow*HSTR + acol] = ra;
        uint4 wv;
        wv.x = packh2(rw0.x, rw0.y); wv.y = packh2(rw0.z, rw0.w);
        wv.z = packh2(rw1.x, rw1.y); wv.w = packh2(rw1.z, rw1.w);
        *(uint4*)&Wh[wrow*HSTR + wcol] = wv;
    }
    __syncthreads();

    for (int s = 0; s < 16; s++) {
        int p = s & 1;
        if (s < 15) {
            int k0 = (s+1)*32;
            ra  = *(const uint2*)(A + (size_t)(m0+arow)*NE + k0 + acol);
            rw0 = *(const float4*)(W + (size_t)(n0+wrow)*NE + k0 + wcol);
            rw1 = *(const float4*)(W + (size_t)(n0+wrow)*NE + k0 + wcol + 4);
        }
        const __half* Ap = Ah + p*AH_ST;
        const __half* Wp = Wh + p*WH_ST;
#pragma unroll
        for (int kt = 0; kt < 2; kt++) {
            uint32_t a[4];
            const __half* ab = Ap + (wm*16)*HSTR + kt*16;
            a[0] = *(const uint32_t*)&ab[g*HSTR + 2*tg];
            a[1] = *(const uint32_t*)&ab[(g+8)*HSTR + 2*tg];
            a[2] = *(const uint32_t*)&ab[g*HSTR + 2*tg + 8];
            a[3] = *(const uint32_t*)&ab[(g+8)*HSTR + 2*tg + 8];
#pragma unroll
            for (int nt = 0; nt < 2; nt++) {
                const __half* wb = Wp + (wn*16 + nt*8 + g)*HSTR + kt*16;
                uint32_t bb[2];
                bb[0] = *(const uint32_t*)&wb[2*tg];
                bb[1] = *(const uint32_t*)&wb[2*tg + 8];
                mma_f16(acc[nt], a, bb);
            }
        }
        if (s < 15) {
            *(uint2*)&Ah[(1-p)*AH_ST + arow*HSTR + acol] = ra;
            uint4 wv;
            wv.x = packh2(rw0.x, rw0.y); wv.y = packh2(rw0.z, rw0.w);
            wv.z = packh2(rw1.x, rw1.y); wv.w = packh2(rw1.z, rw1.w);
            *(uint4*)&Wh[(1-p)*WH_ST + wrow*HSTR + wcol] = wv;
        }
        __syncthreads();
    }
}

__global__ __launch_bounds__(256) void qkv_tc_kernel(
    const float* __restrict__ Wq, const float* __restrict__ bq,
    const float* __restrict__ Wk, const float* __restrict__ bk,
    const float* __restrict__ Wv, const float* __restrict__ bv)
{
    __shared__ __half Ah[2*AH_ST];
    __shared__ __half Wh[2*WH_ST];
    const int mode = blockIdx.z;
    const float* W    = (mode == 0) ? Wq : ((mode == 1) ? Wk : Wv);
    const float* bias = (mode == 0) ? bq : ((mode == 1) ? bk : bv);
    const int m0 = blockIdx.y*32, n0 = blockIdx.x*64;

    float acc[2][4];
    gemm_f16_core(g_x, W, m0, n0, Ah, Wh, acc);

    const int lane = threadIdx.x & 31, g = lane >> 2, tg = lane & 3;
    const int warp = threadIdx.x >> 5, wm = warp >> 2, wn = warp & 3;
    const float QSCALE = 0.125f * 1.44269504088896f;   // 1/sqrt(64) * log2(e)
#pragma unroll
    for (int nt = 0; nt < 2; nt++) {
#pragma unroll
        for (int i = 0; i < 4; i++) {
            int m = m0 + wm*16 + g + (i >= 2 ? 8 : 0);
            int n = n0 + wn*16 + nt*8 + 2*tg + (i & 1);
            float v = acc[nt][i] + bias[n];
            int b = m >> 8, s = m & 255;
            int hh = n >> 6, d = n & 63;
            int l = NOLD + s*NH + hh;
            if (mode == 0)      g_q[m*NE + n] = __float2half_rn(v * QSCALE);
            else if (mode == 1) g_k[(size_t)(b*NL + l)*NDH + d] = __float2half_rn(v);
            else                g_v[(size_t)(b*NDH + d)*NL + l] = __float2half_rn(v);
        }
    }
}

__global__ __launch_bounds__(256) void out_tc_kernel(
    const float* __restrict__ Wo, const float* __restrict__ bo,
    float* __restrict__ out)
{
    __shared__ __half Ah[2*AH_ST];
    __shared__ __half Wh[2*WH_ST];
    const int m0 = blockIdx.y*32, n0 = blockIdx.x*64;
    float acc[2][4];
    gemm_f16_core(g_attn_h, Wo, m0, n0, Ah, Wh, acc);

    const int lane = threadIdx.x & 31, g = lane >> 2, tg = lane & 3;
    const int warp = threadIdx.x >> 5, wm = warp >> 2, wn = warp & 3;
#pragma unroll
    for (int nt = 0; nt < 2; nt++) {
        int r0 = m0 + wm*16 + g;
        int c  = n0 + wn*16 + nt*8 + 2*tg;
        *(float2*)(out + (size_t)r0*NE + c) =
            make_float2(acc[nt][0] + bo[c], acc[nt][1] + bo[c+1]);
        *(float2*)(out + (size_t)(r0+8)*NE + c) =
            make_float2(acc[nt][2] + bo[c], acc[nt][3] + bo[c+1]);
    }
}

// ---------------------------------------------------------------------------
// fp16 flash attention, QT=64, ldmatrix B-fragments, register softmax via
// ex2.approx.f32 (fixed max, log2-domain Q), exp interleaved with PV mma.
// Block = (64 q, h, b*4+lh); 256 threads, 8 warps = 4m x 2n.
// smem halves: Qs[64][72] | Ks 2x[128][72] | Vt 2x[64][136] = 80896 B.
// ---------------------------------------------------------------------------
#define FLASH_SMEM 80896
#define QS_H  (64*72)
#define KS_H  (128*72)
#define VT_H  (64*136)
#define KS_BYTES (KS_H*2)
#define VT_BYTES (VT_H*2)

__global__ __launch_bounds__(256, 2) void flash_f16_kernel()
{
    extern __shared__ __half smh[];
    __half* Qs = smh;                    // [64][72]
    __half* Ks = smh + QS_H;             // 2 x [128][72]
    __half* Vt = smh + QS_H + 2*KS_H;    // 2 x [64][136]
    float* red  = (float*)(smh + QS_H);  // epilogue reuse: [2][64][64]
    float* lred = red + 2*64*64;         // [2][64]

    const int t = threadIdx.x;
    const int lane = t & 31, g = lane>>2, tg = lane&3;
    const int warp = t>>5, wm = warp>>1, wn = warp&1;
    const int bz = blockIdx.z, b = bz>>2, lh = bz&3;
    const int h = blockIdx.y, q0 = blockIdx.x*64;

    {   // load Q tile (prescaled fp16, log2-domain): 64x64 halves
        int q = t>>2, oct = t&3;
        const uint4* src = (const uint4*)g_q +
            (size_t)((b*NS + q0 + q)*NE + h*64)/8 + oct*2;
        *(uint4*)&Qs[q*72 + oct*16]     = src[0];
        *(uint4*)&Qs[q*72 + oct*16 + 8] = src[1];
    }

    const __half* kg = g_k + (size_t)b*NL*64;
    const __half* vg = g_v + (size_t)b*64*NL;
    const int l0base = lh*NCH2*FKT;
    const int krow = t>>1, khb = t&1;
    const int vrow = t>>2, vq = t&3;
    uint32_t ks_dst = (uint32_t)__cvta_generic_to_shared(&Ks[krow*72 + khb*32]);
    uint32_t vt_dst = (uint32_t)__cvta_generic_to_shared(&Vt[vrow*136 + vq*32]);
    const __half* ksrc = kg + (size_t)krow*64 + khb*32;   // + l0*64
    const __half* vsrc = vg + (size_t)vrow*NL + vq*32;    // + l0

    // ldmatrix per-lane source addresses (buffer 0)
    const int lrow = lane & 7, lmat = lane >> 3;
    uint32_t qk_src = (uint32_t)__cvta_generic_to_shared(
        &Ks[(wn*64 + lrow)*72 + lmat*8]);
    uint32_t pv_src = (uint32_t)__cvta_generic_to_shared(
        &Vt[lrow*136 + wn*64 + lmat*8]);

    {   // prologue: chunk 0 -> buffers[0]
        const __half* ks0 = ksrc + (size_t)l0base*64;
        const __half* vs0 = vsrc + l0base;
#pragma unroll
        for (int i = 0; i < 4; i++) { CP16(ks_dst + i*16, ks0 + i*8); }
#pragma unroll
        for (int i = 0; i < 4; i++) { CP16(vt_dst + i*16, vs0 + i*8); }
        CP_COMMIT(); CP_WAIT0();
    }
    __syncthreads();   // also publishes Qs

    // hoist Q fragments (warp's 16 rows)
    uint32_t qa[4][4];
#pragma unroll
    for (int kt = 0; kt < 4; kt++) {
        const __half* base = Qs + (wm*16)*72 + kt*16;
        qa[kt][0] = *(const uint32_t*)&base[g*72 + 2*tg];
        qa[kt][1] = *(const uint32_t*)&base[(g+8)*72 + 2*tg];
        qa[kt][2] = *(const uint32_t*)&base[g*72 + 2*tg + 8];
        qa[kt][3] = *(const uint32_t*)&base[(g+8)*72 + 2*tg + 8];
    }

    float o[8][4];
#pragma unroll
    for (int nd = 0; nd < 8; nd++)
#pragma unroll
        for (int i = 0; i < 4; i++) o[nd][i] = 0.f;
    float lp0 = 0.f, lp1 = 0.f;

    for (int ch = 0; ch < NCH2; ch++) {
        const int p = ch & 1;
        if (ch + 1 < NCH2) {   // cp.async next chunk into buffers[1-p]
            int l0 = l0base + (ch+1)*FKT;
            uint32_t kd = ks_dst + (1-p)*KS_BYTES;
            uint32_t vd = vt_dst + (1-p)*VT_BYTES;
            const __half* ks2 = ksrc + (size_t)l0*64;
            const __half* vs2 = vsrc + l0;
#pragma unroll
            for (int i = 0; i < 4; i++) { CP16(kd + i*16, ks2 + i*8); }
#pragma unroll
            for (int i = 0; i < 4; i++) { CP16(vd + i*16, vs2 + i*8); }
        }
        CP_COMMIT();

        // ---- QK: warp's 16 rows x 64-key strip (ldmatrix B-frags) ----
        const uint32_t qk_p = qk_src + p*KS_BYTES;
        float sc[8][4];
#pragma unroll
        for (int nt = 0; nt < 8; nt++)
#pragma unroll
            for (int i = 0; i < 4; i++) sc[nt][i] = 0.f;
#pragma unroll
        for (int nt = 0; nt < 8; nt++) {
#pragma unroll
            for (int ktp = 0; ktp < 2; ktp++) {
                uint32_t bq[4];
                ldsm4(bq, qk_p + (nt*8*72 + ktp*32)*2);
                mma_f16(sc[nt], qa[2*ktp],   &bq[0]);
                mma_f16(sc[nt], qa[2*ktp+1], &bq[2]);
            }
        }

        // ---- exp (interleaved with PV): per 32-key half-strip ----
        const uint32_t pv_p = pv_src + p*VT_BYTES;
#pragma unroll
        for (int jp = 0; jp < 2; jp++) {
            uint32_t pa[2][4];
#pragma unroll
            for (int jj = 0; jj < 2; jj++) {
                int j = 2*jp + jj;
                float e00 = ex2f(sc[2*j][0]),   e01 = ex2f(sc[2*j][1]);
                float e02 = ex2f(sc[2*j][2]),   e03 = ex2f(sc[2*j][3]);
                float e10 = ex2f(sc[2*j+1][0]), e11 = ex2f(sc[2*j+1][1]);
                float e12 = ex2f(sc[2*j+1][2]), e13 = ex2f(sc[2*j+1][3]);
                lp0 += e00 + e01 + e10 + e11;   // row wm*16+g
                lp1 += e02 + e03 + e12 + e13;   // row wm*16+g+8
                pa[jj][0] = packh2(e00, e01);
                pa[jj][1] = packh2(e02, e03);
                pa[jj][2] = packh2(e10, e11);
                pa[jj][3] = packh2(e12, e13);
            }
            // PV for this 32-key half-strip, all 64 dims (ldmatrix B-frags)
#pragma unroll
            for (int nd = 0; nd < 8; nd++) {
                uint32_t bv[4];
                ldsm4(bv, pv_p + (nd*8*136 + jp*32)*2);
                mma_f16(o[nd], pa[0], &bv[0]);
                mma_f16(o[nd], pa[1], &bv[2]);
            }
        }

        CP_WAIT0();
        __syncthreads();
    }

    // ---- epilogue: cross-wn O reduction (red reuses K/V smem) ----
#pragma unroll
    for (int nd = 0; nd < 8; nd++) {
        float* r0 = &red[(size_t)(wn*64 + wm*16 + g)*64 + nd*8 + 2*tg];
        r0[0] = o[nd][0]; r0[1] = o[nd][1];
        float* r1 = r0 + 8*64;
        r1[0] = o[nd][2]; r1[1] = o[nd][3];
    }
    lp0 += __shfl_xor_sync(0xffffffffu, lp0, 1);
    lp0 += __shfl_xor_sync(0xffffffffu, lp0, 2);
    lp1 += __shfl_xor_sync(0xffffffffu, lp1, 1);
    lp1 += __shfl_xor_sync(0xffffffffu, lp1, 2);
    if (tg == 0) {
        lred[wn*64 + wm*16 + g]     = lp0;
        lred[wn*64 + wm*16 + g + 8] = lp1;
    }
    __syncthreads();

    {
        int row = t>>2, dc = (t&3)*16;
        float4 s[4];
#pragma unroll
        for (int i = 0; i < 4; i++) {
            float4 a0 = *(const float4*)&red[(size_t)row*64 + dc + i*4];
            float4 a1 = *(const float4*)&red[(size_t)(64 + row)*64 + dc + i*4];
            s[i].x = a0.x + a1.x; s[i].y = a0.y + a1.y;
            s[i].z = a0.z + a1.z; s[i].w = a0.w + a1.w;
        }
        float* po = g_po + (size_t)lh*(NB*NS*NE) +
                    (size_t)(b*NS + q0 + row)*NE + h*64 + dc;
#pragma unroll
        for (int i = 0; i < 4; i++) *(float4*)(po + i*4) = s[i];
    }
    if (t < 64)
        g_pl[lh*(NB*NH*NS) + (b*NH + h)*NS + q0 + t] = lred[t] + lred[64 + t];
}

// ---------------------------------------------------------------------------
// Merge 4 partials: attn = sum(O_s) / sum(l_s), stored fp16 for out-proj.
// ---------------------------------------------------------------------------
__global__ void merge_kernel()
{
    int i = blockIdx.x*blockDim.x + threadIdx.x;    // over NB*NS*NE/4
    if (i >= NB*NS*NE/4) return;
    int dq = i & 15;
    int h  = (i >> 4) & 7;
    int q  = (i >> 7) & 255;
    int b  = i >> 15;
    int rml = (b*NH + h)*NS + q;
    float lsum = 0.f;
#pragma unroll
    for (int s = 0; s < FSPLIT; s++) lsum += g_pl[s*(NB*NH*NS) + rml];
    float inv = 1.f / lsum;
    int off4 = ((b*NS + q)*NE + h*NDH + dq*4) >> 2;
    float4 acc = make_float4(0.f, 0.f, 0.f, 0.f);
#pragma unroll
    for (int s = 0; s < FSPLIT; s++) {
        float4 ov = ((const float4*)(g_po + (size_t)s*NB*NS*NE))[off4];
        acc.x += ov.x; acc.y += ov.y; acc.z += ov.z; acc.w += ov.w;
    }
    uint2 r;
    r.x = packh2(acc.x*inv, acc.y*inv);
    r.y = packh2(acc.z*inv, acc.w*inv);
    ((uint2*)g_attn_h)[off4] = r;
}

// ---------------------------------------------------------------------------
extern "C" void kernel_launch(void* const* d_in, const int* in_sizes, int n_in,
                              void* d_out, int out_size)
{
    const float* x  = (const float*)d_in[0];
    const float* kc = (const float*)d_in[1];
    const float* vc = (const float*)d_in[2];
    const float* Wq = (const float*)d_in[3];
    const float* bq = (const float*)d_in[4];
    const float* Wk = (const float*)d_in[5];
    const float* bk = (const float*)d_in[6];
    const float* Wv = (const float*)d_in[7];
    const float* bv = (const float*)d_in[8];
    const float* Wo = (const float*)d_in[9];
    const float* bo = (const float*)d_in[10];
    float* out = (float*)d_out;

    cudaFuncSetAttribute(flash_f16_kernel,
                         cudaFuncAttributeMaxDynamicSharedMemorySize,
                         FLASH_SMEM);

    convert_x_kernel<<<NB*NS*NE/8/256, 256>>>((const float4*)x);

    copy_cache_kernel<<<dim3(NOLD/64, NB), 256>>>(
        (const float4*)kc, (const float4*)vc);

    qkv_tc_kernel<<<dim3(8, 16, 3), 256>>>(Wq, bq, Wk, bk, Wv, bv);

    flash_f16_kernel<<<dim3(NS/64, NH, NB*FSPLIT), 256, FLASH_SMEM>>>();

    merge_kernel<<<(NB*NS*NE/4 + 255)/256, 256>>>();

    out_tc_kernel<<<dim3(8, 16), 256>>>(Wo, bo, out);
}